// round 1
// baseline (speedup 1.0000x reference)
#include <cuda_runtime.h>
#include <cstdint>
#include <cstddef>

// Problem constants (shapes fixed by the dataset)
#define N_TOT 16384      // B*H*W = 16*32*32
#define M_TOT 4096
#define KDIM  64
#define NCHUNK 64
#define ROWS_PER_CHUNK (N_TOT / NCHUNK)   // 256

// ---------------- device scratch (static, no allocs) ----------------
__device__ float    g_zf[(size_t)N_TOT * KDIM];      // 4 MB, transposed z
__device__ float    g_zsq[N_TOT];
__device__ float    g_esq[M_TOT];
__device__ unsigned g_wmax[M_TOT];                   // max(belong^2 * d2) bits
__device__ float    g_t[M_TOT];                      // new_max
__device__ float    g_t2[M_TOT];                     // new_max^2
__device__ float    g_d2[(size_t)N_TOT * M_TOT];     // 256 MB distance^2
__device__ float    g_pmin[NCHUNK * M_TOT];
__device__ float    g_psum[NCHUNK * M_TOT];
__device__ float    g_lse[M_TOT];

// ---------------- helpers ----------------
__device__ __forceinline__ unsigned f2tf32(float x) {
    unsigned r;
    asm("cvt.rna.tf32.f32 %0, %1;" : "=r"(r) : "f"(x));
    return r;
}

__device__ __forceinline__ void mma_tf32(float c[4], const unsigned a[4], const unsigned b[2]) {
    asm volatile(
        "mma.sync.aligned.m16n8k8.row.col.f32.tf32.tf32.f32 "
        "{%0,%1,%2,%3}, {%4,%5,%6,%7}, {%8,%9}, {%0,%1,%2,%3};"
        : "+f"(c[0]), "+f"(c[1]), "+f"(c[2]), "+f"(c[3])
        : "r"(a[0]), "r"(a[1]), "r"(a[2]), "r"(a[3]),
          "r"(b[0]), "r"(b[1]));
}

// ---------------- kernel 1: transpose z -> zf [N, K] ----------------
__global__ void prep_zf(const float* __restrict__ z) {
    int idx = blockIdx.x * 256 + threadIdx.x;   // coalesced read of z
    // z layout: [B=16][C=64][H=32][W=32]
    int w = idx & 31;
    int h = (idx >> 5) & 31;
    int c = (idx >> 10) & 63;
    int b = idx >> 16;
    int n = (b << 10) + (h << 5) + w;
    g_zf[(size_t)n * KDIM + c] = z[idx];
}

// ---------------- kernel 2: row norms + wmax reset ----------------
__global__ void prep_norms(const float* __restrict__ e) {
    int i = blockIdx.x * 256 + threadIdx.x;     // grid covers N_TOT
    if (i < N_TOT) {
        const float4* p = (const float4*)(g_zf + (size_t)i * KDIM);
        float ax = 0.f, ay = 0.f, az = 0.f, aw = 0.f;
        #pragma unroll
        for (int k = 0; k < 16; k++) {
            float4 v = p[k];
            ax += v.x * v.x; ay += v.y * v.y; az += v.z * v.z; aw += v.w * v.w;
        }
        g_zsq[i] = (ax + ay) + (az + aw);
    }
    if (i < M_TOT) {
        const float4* p = (const float4*)(e + (size_t)i * KDIM);
        float ax = 0.f, ay = 0.f, az = 0.f, aw = 0.f;
        #pragma unroll
        for (int k = 0; k < 16; k++) {
            float4 v = p[k];
            ax += v.x * v.x; ay += v.y * v.y; az += v.z * v.z; aw += v.w * v.w;
        }
        g_esq[i] = (ax + ay) + (az + aw);
        g_wmax[i] = 0u;   // reset for this launch (graph replays)
    }
}

// ---------------- kernel 3: tf32 GEMM + d2 store + belong^2*d2 colmax ----------------
// Tile: 128 (n) x 128 (m), K=64 in one shot. 8 warps, warp tile 64x32.
#define SPAD 68   // padded row stride (floats) -> conflict-free frag loads

__global__ __launch_bounds__(256) void gemm_pass1(const float* __restrict__ e,
                                                  const float* __restrict__ belong) {
    extern __shared__ unsigned sm[];
    unsigned* As = sm;                       // 128 * 68
    unsigned* Bs = sm + 128 * SPAD;          // 128 * 68
    float* szsq = (float*)(sm + 2 * 128 * SPAD);   // 128
    float* sesq = szsq + 128;                      // 128

    const int tid = threadIdx.x;
    const int m0 = blockIdx.x * 128;
    const int n0 = blockIdx.y * 128;

    // stage A = zf tile, B = e tile (convert to tf32 with round-to-nearest)
    #pragma unroll
    for (int it = 0; it < 8; it++) {
        int idx = tid + it * 256;            // 0..2047 float4 slots
        int row = idx >> 4, c4 = idx & 15;
        float4 v = *(const float4*)(g_zf + (size_t)(n0 + row) * KDIM + c4 * 4);
        uint4 u = make_uint4(f2tf32(v.x), f2tf32(v.y), f2tf32(v.z), f2tf32(v.w));
        *(uint4*)(As + row * SPAD + c4 * 4) = u;
    }
    #pragma unroll
    for (int it = 0; it < 8; it++) {
        int idx = tid + it * 256;
        int row = idx >> 4, c4 = idx & 15;
        float4 v = *(const float4*)(e + (size_t)(m0 + row) * KDIM + c4 * 4);
        uint4 u = make_uint4(f2tf32(v.x), f2tf32(v.y), f2tf32(v.z), f2tf32(v.w));
        *(uint4*)(Bs + row * SPAD + c4 * 4) = u;
    }
    if (tid < 128) {
        szsq[tid] = g_zsq[n0 + tid];
        sesq[tid] = g_esq[m0 + tid];
    }
    __syncthreads();

    const int lane = tid & 31, wid = tid >> 5;
    const int wm = wid >> 2;       // 0..1 (n-rows halves)
    const int wn = wid & 3;        // 0..3 (m-col quarters)
    const int ar = lane >> 2, ac = lane & 3;

    float acc[4][4][4];
    #pragma unroll
    for (int i = 0; i < 4; i++)
        #pragma unroll
        for (int j = 0; j < 4; j++)
            #pragma unroll
            for (int r = 0; r < 4; r++) acc[i][j][r] = 0.f;

    #pragma unroll
    for (int ks = 0; ks < 8; ks++) {
        const int k0 = ks * 8;
        unsigned a[4][4], b[4][2];
        #pragma unroll
        for (int i = 0; i < 4; i++) {
            int rb = wm * 64 + i * 16 + ar;
            a[i][0] = As[rb * SPAD + k0 + ac];
            a[i][1] = As[(rb + 8) * SPAD + k0 + ac];
            a[i][2] = As[rb * SPAD + k0 + ac + 4];
            a[i][3] = As[(rb + 8) * SPAD + k0 + ac + 4];
        }
        #pragma unroll
        for (int j = 0; j < 4; j++) {
            int cb = wn * 32 + j * 8 + ar;
            b[j][0] = Bs[cb * SPAD + k0 + ac];
            b[j][1] = Bs[cb * SPAD + k0 + ac + 4];
        }
        #pragma unroll
        for (int i = 0; i < 4; i++)
            #pragma unroll
            for (int j = 0; j < 4; j++)
                mma_tf32(acc[i][j], a[i], b[j]);
    }

    // epilogue: d2 = zsq + esq - 2*dot (clamped), store d2, track max(b^2*d2) per col
    float wloc[4][2];
    #pragma unroll
    for (int j = 0; j < 4; j++) { wloc[j][0] = 0.f; wloc[j][1] = 0.f; }

    #pragma unroll
    for (int i = 0; i < 4; i++) {
        int lr0 = wm * 64 + i * 16 + ar;
        int lr1 = lr0 + 8;
        float zs0 = szsq[lr0], zs1 = szsq[lr1];
        size_t gr0 = (size_t)(n0 + lr0) * M_TOT;
        size_t gr1 = (size_t)(n0 + lr1) * M_TOT;
        #pragma unroll
        for (int j = 0; j < 4; j++) {
            int lc = wn * 32 + j * 8 + 2 * ac;
            int gc = m0 + lc;
            float es0 = sesq[lc], es1 = sesq[lc + 1];
            float d00 = fmaxf(zs0 + es0 - 2.f * acc[i][j][0], 0.f);
            float d01 = fmaxf(zs0 + es1 - 2.f * acc[i][j][1], 0.f);
            float d10 = fmaxf(zs1 + es0 - 2.f * acc[i][j][2], 0.f);
            float d11 = fmaxf(zs1 + es1 - 2.f * acc[i][j][3], 0.f);
            *(float2*)(g_d2 + gr0 + gc) = make_float2(d00, d01);
            *(float2*)(g_d2 + gr1 + gc) = make_float2(d10, d11);
            float2 b0 = *(const float2*)(belong + gr0 + gc);
            float2 b1 = *(const float2*)(belong + gr1 + gc);
            wloc[j][0] = fmaxf(wloc[j][0], fmaxf(b0.x * b0.x * d00, b1.x * b1.x * d10));
            wloc[j][1] = fmaxf(wloc[j][1], fmaxf(b0.y * b0.y * d01, b1.y * b1.y * d11));
        }
    }

    // reduce over lanes sharing lane%4, then atomic max per column (floats >= 0)
    #pragma unroll
    for (int j = 0; j < 4; j++) {
        #pragma unroll
        for (int par = 0; par < 2; par++) {
            float v = wloc[j][par];
            #pragma unroll
            for (int off = 4; off < 32; off <<= 1)
                v = fmaxf(v, __shfl_xor_sync(0xffffffffu, v, off));
            if (lane < 4)
                atomicMax(&g_wmax[m0 + wn * 32 + j * 8 + 2 * lane + par],
                          __float_as_uint(v));
        }
    }
}

// ---------------- kernel 4: new_max per code ----------------
__global__ void newmax_k(const float* __restrict__ maxd) {
    int i = blockIdx.x * 256 + threadIdx.x;
    float w = __uint_as_float(g_wmax[i]);
    float bm = sqrtf(w);                                 // batch_max
    float nm = 0.999f * maxd[i] + 0.001f * bm;           // EMA update
    nm = fmaxf(nm, 1e-8f);                               // clip(EPS, None)
    g_t[i] = nm;
    g_t2[i] = nm * nm;
}

// ---------------- kernel 5: per-column online logsumexp partials ----------------
__global__ __launch_bounds__(256) void pass2(const float* __restrict__ lsig,
                                             const int* __restrict__ pptr,
                                             int has_p) {
    int m = blockIdx.x * 256 + threadIdx.x;
    int chunk = blockIdx.y;
    float ls = lsig[0];
    float alpha = -0.5f * __expf(-2.f * ls);    // -1/(2*exp(ls)^2)

    int praw = has_p ? *pptr : 2;
    float pf = (praw > 0 && praw < 1000) ? (float)praw : __int_as_float(praw);
    bool fast = (pf == 2.0f);
    float elo = 2.f / pf, ehi = 2.f * pf;

    float t = g_t[m], t2v = g_t2[m];
    float vmin = 3.0e38f, s = 0.f;
    const float* col = g_d2 + (size_t)chunk * ROWS_PER_CHUNK * M_TOT + m;

    for (int r = 0; r < ROWS_PER_CHUNK; r++) {
        float d2 = col[(size_t)r * M_TOT];
        float v;
        if (fast) {
            v = (d2 < t2v) ? sqrtf(d2) : d2 * d2;
        } else {
            float dd = sqrtf(d2);
            v = (dd < t) ? __powf(dd, elo) : __powf(dd, ehi);
        }
        if (v < vmin) {
            s = s * __expf(alpha * (vmin - v)) + 1.f;   // rescale (rare)
            vmin = v;
        } else {
            float a = alpha * (v - vmin);
            if (a > -30.f) s += __expf(a);              // else underflows in ref too
        }
    }
    g_pmin[chunk * M_TOT + m] = vmin;
    g_psum[chunk * M_TOT + m] = s;
}

// ---------------- kernel 6: combine partials -> lse per column ----------------
__global__ void combine_k(const float* __restrict__ lsig) {
    int m = blockIdx.x * 256 + threadIdx.x;
    float ls = lsig[0];
    float alpha = -0.5f * __expf(-2.f * ls);
    float vmin = 3.0e38f;
    #pragma unroll 4
    for (int c = 0; c < NCHUNK; c++)
        vmin = fminf(vmin, g_pmin[c * M_TOT + m]);
    float s = 0.f;
    #pragma unroll 4
    for (int c = 0; c < NCHUNK; c++) {
        float a = alpha * (g_pmin[c * M_TOT + m] - vmin);
        s += g_psum[c * M_TOT + m] * __expf(a);
    }
    g_lse[m] = alpha * vmin + logf(s);
}

// ---------------- kernel 7: final reduction -> loss ----------------
__global__ void final_k(const float* __restrict__ lsig, float* __restrict__ out) {
    __shared__ double red[256];
    double a = 0.0;
    for (int i = threadIdx.x; i < M_TOT; i += 256) a += (double)g_lse[i];
    red[threadIdx.x] = a;
    __syncthreads();
    for (int st = 128; st > 0; st >>= 1) {
        if (threadIdx.x < st) red[threadIdx.x] += red[threadIdx.x + st];
        __syncthreads();
    }
    if (threadIdx.x == 0) {
        double ls = (double)lsig[0];
        out[0] = (float)(-(red[0] / (double)M_TOT) + (double)KDIM * ls);
    }
}

// ---------------- launch ----------------
extern "C" void kernel_launch(void* const* d_in, const int* in_sizes, int n_in,
                              void* d_out, int out_size) {
    const float* z      = (const float*)d_in[0];
    const float* e      = (const float*)d_in[1];
    const float* belong = (const float*)d_in[2];
    const float* lsig   = (const float*)d_in[3];
    const float* maxd   = (const float*)d_in[4];
    const int*   pptr   = (n_in > 5) ? (const int*)d_in[5] : nullptr;
    (void)in_sizes; (void)out_size;

    const int smem_bytes = (2 * 128 * SPAD + 256) * 4;   // 70656
    cudaFuncSetAttribute(gemm_pass1, cudaFuncAttributeMaxDynamicSharedMemorySize,
                         smem_bytes);

    prep_zf<<<4096, 256>>>(z);
    prep_norms<<<64, 256>>>(e);
    gemm_pass1<<<dim3(M_TOT / 128, N_TOT / 128), 256, smem_bytes>>>(e, belong);
    newmax_k<<<M_TOT / 256, 256>>>(maxd);
    pass2<<<dim3(M_TOT / 256, NCHUNK), 256>>>(lsig, pptr, pptr ? 1 : 0);
    combine_k<<<M_TOT / 256, 256>>>(lsig);
    final_k<<<1, 256>>>(lsig, (float*)d_out);
}

// round 2
// speedup vs baseline: 1.1393x; 1.1393x over previous
#include <cuda_runtime.h>
#include <cstdint>
#include <cstddef>

// Problem constants (shapes fixed by the dataset)
#define N_TOT 16384      // B*H*W = 16*32*32
#define M_TOT 4096
#define KDIM  64
#define NCHUNK 128
#define ROWS_PER_CHUNK (N_TOT / NCHUNK)   // 128

// ---------------- device scratch (static, no allocs) ----------------
__device__ float    g_zf[(size_t)N_TOT * KDIM];      // 4 MB, transposed z
__device__ float    g_zsq[N_TOT];
__device__ float    g_esq[M_TOT];
__device__ unsigned g_wmax[M_TOT];                   // max(belong^2 * d2) bits
__device__ float    g_t[M_TOT];                      // new_max
__device__ float    g_t2[M_TOT];                     // new_max^2
__device__ float    g_d2[(size_t)N_TOT * M_TOT];     // 256 MB distance^2
__device__ float    g_pmin[NCHUNK * M_TOT];
__device__ float    g_psum[NCHUNK * M_TOT];
__device__ float    g_lse[M_TOT];

// ---------------- helpers ----------------
__device__ __forceinline__ unsigned f2tf32(float x) {
    unsigned r;
    asm("cvt.rna.tf32.f32 %0, %1;" : "=r"(r) : "f"(x));
    return r;
}

__device__ __forceinline__ void mma_tf32(float c[4], const unsigned a[4], const unsigned b[2]) {
    asm volatile(
        "mma.sync.aligned.m16n8k8.row.col.f32.tf32.tf32.f32 "
        "{%0,%1,%2,%3}, {%4,%5,%6,%7}, {%8,%9}, {%0,%1,%2,%3};"
        : "+f"(c[0]), "+f"(c[1]), "+f"(c[2]), "+f"(c[3])
        : "r"(a[0]), "r"(a[1]), "r"(a[2]), "r"(a[3]),
          "r"(b[0]), "r"(b[1]));
}

// ---------------- kernel 1: transpose z -> zf [N, K] ----------------
__global__ void prep_zf(const float* __restrict__ z) {
    int idx = blockIdx.x * 256 + threadIdx.x;   // coalesced read of z
    // z layout: [B=16][C=64][H=32][W=32]
    int w = idx & 31;
    int h = (idx >> 5) & 31;
    int c = (idx >> 10) & 63;
    int b = idx >> 16;
    int n = (b << 10) + (h << 5) + w;
    g_zf[(size_t)n * KDIM + c] = z[idx];
}

// ---------------- kernel 2: row norms + wmax reset ----------------
__global__ void prep_norms(const float* __restrict__ e) {
    int i = blockIdx.x * 256 + threadIdx.x;     // grid covers N_TOT
    if (i < N_TOT) {
        const float4* p = (const float4*)(g_zf + (size_t)i * KDIM);
        float ax = 0.f, ay = 0.f, az = 0.f, aw = 0.f;
        #pragma unroll
        for (int k = 0; k < 16; k++) {
            float4 v = p[k];
            ax += v.x * v.x; ay += v.y * v.y; az += v.z * v.z; aw += v.w * v.w;
        }
        g_zsq[i] = (ax + ay) + (az + aw);
    }
    if (i < M_TOT) {
        const float4* p = (const float4*)(e + (size_t)i * KDIM);
        float ax = 0.f, ay = 0.f, az = 0.f, aw = 0.f;
        #pragma unroll
        for (int k = 0; k < 16; k++) {
            float4 v = p[k];
            ax += v.x * v.x; ay += v.y * v.y; az += v.z * v.z; aw += v.w * v.w;
        }
        g_esq[i] = (ax + ay) + (az + aw);
        g_wmax[i] = 0u;   // reset for this launch (graph replays)
    }
}

// ---------------- kernel 3: tf32 GEMM + d2 store + belong^2*d2 colmax ----------------
// Tile: 128 (n) x 128 (m), K=64 in one shot. 8 warps, warp tile 64x32.
#define SPAD 68   // padded row stride (floats) -> conflict-free frag loads

__global__ __launch_bounds__(256) void gemm_pass1(const float* __restrict__ e,
                                                  const float* __restrict__ belong) {
    extern __shared__ unsigned sm[];
    unsigned* As = sm;                       // 128 * 68
    unsigned* Bs = sm + 128 * SPAD;          // 128 * 68
    float* szsq = (float*)(sm + 2 * 128 * SPAD);   // 128
    float* sesq = szsq + 128;                      // 128

    const int tid = threadIdx.x;
    const int m0 = blockIdx.x * 128;
    const int n0 = blockIdx.y * 128;

    // stage A = zf tile, B = e tile (convert to tf32 with round-to-nearest)
    #pragma unroll
    for (int it = 0; it < 8; it++) {
        int idx = tid + it * 256;            // 0..2047 float4 slots
        int row = idx >> 4, c4 = idx & 15;
        float4 v = *(const float4*)(g_zf + (size_t)(n0 + row) * KDIM + c4 * 4);
        uint4 u = make_uint4(f2tf32(v.x), f2tf32(v.y), f2tf32(v.z), f2tf32(v.w));
        *(uint4*)(As + row * SPAD + c4 * 4) = u;
    }
    #pragma unroll
    for (int it = 0; it < 8; it++) {
        int idx = tid + it * 256;
        int row = idx >> 4, c4 = idx & 15;
        float4 v = *(const float4*)(e + (size_t)(m0 + row) * KDIM + c4 * 4);
        uint4 u = make_uint4(f2tf32(v.x), f2tf32(v.y), f2tf32(v.z), f2tf32(v.w));
        *(uint4*)(Bs + row * SPAD + c4 * 4) = u;
    }
    if (tid < 128) {
        szsq[tid] = g_zsq[n0 + tid];
        sesq[tid] = g_esq[m0 + tid];
    }
    __syncthreads();

    const int lane = tid & 31, wid = tid >> 5;
    const int wm = wid >> 2;       // 0..1 (n-rows halves)
    const int wn = wid & 3;        // 0..3 (m-col quarters)
    const int ar = lane >> 2, ac = lane & 3;

    float acc[4][4][4];
    #pragma unroll
    for (int i = 0; i < 4; i++)
        #pragma unroll
        for (int j = 0; j < 4; j++)
            #pragma unroll
            for (int r = 0; r < 4; r++) acc[i][j][r] = 0.f;

    #pragma unroll
    for (int ks = 0; ks < 8; ks++) {
        const int k0 = ks * 8;
        unsigned a[4][4], b[4][2];
        #pragma unroll
        for (int i = 0; i < 4; i++) {
            int rb = wm * 64 + i * 16 + ar;
            a[i][0] = As[rb * SPAD + k0 + ac];
            a[i][1] = As[(rb + 8) * SPAD + k0 + ac];
            a[i][2] = As[rb * SPAD + k0 + ac + 4];
            a[i][3] = As[(rb + 8) * SPAD + k0 + ac + 4];
        }
        #pragma unroll
        for (int j = 0; j < 4; j++) {
            int cb = wn * 32 + j * 8 + ar;
            b[j][0] = Bs[cb * SPAD + k0 + ac];
            b[j][1] = Bs[cb * SPAD + k0 + ac + 4];
        }
        #pragma unroll
        for (int i = 0; i < 4; i++)
            #pragma unroll
            for (int j = 0; j < 4; j++)
                mma_tf32(acc[i][j], a[i], b[j]);
    }

    // epilogue: d2 = zsq + esq - 2*dot (clamped), store d2, track max(b^2*d2) per col
    float wloc[4][2];
    #pragma unroll
    for (int j = 0; j < 4; j++) { wloc[j][0] = 0.f; wloc[j][1] = 0.f; }

    #pragma unroll
    for (int i = 0; i < 4; i++) {
        int lr0 = wm * 64 + i * 16 + ar;
        int lr1 = lr0 + 8;
        float zs0 = szsq[lr0], zs1 = szsq[lr1];
        size_t gr0 = (size_t)(n0 + lr0) * M_TOT;
        size_t gr1 = (size_t)(n0 + lr1) * M_TOT;
        #pragma unroll
        for (int j = 0; j < 4; j++) {
            int lc = wn * 32 + j * 8 + 2 * ac;
            int gc = m0 + lc;
            float es0 = sesq[lc], es1 = sesq[lc + 1];
            float d00 = fmaxf(zs0 + es0 - 2.f * acc[i][j][0], 0.f);
            float d01 = fmaxf(zs0 + es1 - 2.f * acc[i][j][1], 0.f);
            float d10 = fmaxf(zs1 + es0 - 2.f * acc[i][j][2], 0.f);
            float d11 = fmaxf(zs1 + es1 - 2.f * acc[i][j][3], 0.f);
            *(float2*)(g_d2 + gr0 + gc) = make_float2(d00, d01);
            *(float2*)(g_d2 + gr1 + gc) = make_float2(d10, d11);
            float2 b0 = *(const float2*)(belong + gr0 + gc);
            float2 b1 = *(const float2*)(belong + gr1 + gc);
            wloc[j][0] = fmaxf(wloc[j][0], fmaxf(b0.x * b0.x * d00, b1.x * b1.x * d10));
            wloc[j][1] = fmaxf(wloc[j][1], fmaxf(b0.y * b0.y * d01, b1.y * b1.y * d11));
        }
    }

    // reduce over lanes sharing lane%4, then atomic max per column (floats >= 0)
    #pragma unroll
    for (int j = 0; j < 4; j++) {
        #pragma unroll
        for (int par = 0; par < 2; par++) {
            float v = wloc[j][par];
            #pragma unroll
            for (int off = 4; off < 32; off <<= 1)
                v = fmaxf(v, __shfl_xor_sync(0xffffffffu, v, off));
            if (lane < 4)
                atomicMax(&g_wmax[m0 + wn * 32 + j * 8 + 2 * lane + par],
                          __float_as_uint(v));
        }
    }
}

// ---------------- kernel 4: new_max per code ----------------
__global__ void newmax_k(const float* __restrict__ maxd) {
    int i = blockIdx.x * 256 + threadIdx.x;
    float w = __uint_as_float(g_wmax[i]);
    float bm = sqrtf(w);                                 // batch_max
    float nm = 0.999f * maxd[i] + 0.001f * bm;           // EMA update
    nm = fmaxf(nm, 1e-8f);                               // clip(EPS, None)
    g_t[i] = nm;
    g_t2[i] = nm * nm;
}

// ---------------- kernel 5: per-column online logsumexp partials ----------------
// Each thread owns 4 consecutive columns (one LDG.128 per row). Common path is
// MUFU-free: v = d2*d2 plus two compares. exp/sqrt only in the rare guarded
// slow path (new running min, contribution >= e^-30, or d2 < new_max^2).
__global__ __launch_bounds__(256) void pass2(const float* __restrict__ lsig,
                                             const int* __restrict__ pptr,
                                             int has_p) {
    const int mg = blockIdx.x * 256 + threadIdx.x;   // column group 0..1023
    const int m  = mg * 4;
    const int chunk = blockIdx.y;
    const float ls = lsig[0];
    const float alpha = -0.5f * __expf(-2.f * ls);   // -1/(2*exp(ls)^2), alpha < 0
    const float margin = -30.f / alpha;              // contribution cutoff in v-space

    int praw = has_p ? *pptr : 2;
    float pf = (praw > 0 && praw < 1000) ? (float)praw : __int_as_float(praw);
    const bool fast = (pf == 2.0f);

    const float4 t2v = *(const float4*)(g_t2 + m);
    const float4 tv  = *(const float4*)(g_t + m);

    float vmin[4], s[4], thr[4];
    #pragma unroll
    for (int j = 0; j < 4; j++) { vmin[j] = 3.0e38f; s[j] = 0.f; thr[j] = 3.0e38f; }

    const float* base = g_d2 + (size_t)chunk * ROWS_PER_CHUNK * M_TOT + m;

    if (fast) {
        #pragma unroll 4
        for (int r = 0; r < ROWS_PER_CHUNK; r++) {
            float4 d4 = *(const float4*)(base + (size_t)r * M_TOT);
            float dv[4] = {d4.x, d4.y, d4.z, d4.w};
            float tt[4] = {t2v.x, t2v.y, t2v.z, t2v.w};
            #pragma unroll
            for (int j = 0; j < 4; j++) {
                float d2 = dv[j];
                float v2 = d2 * d2;
                if (v2 < thr[j] || d2 < tt[j]) {     // rare slow path
                    float v = (d2 < tt[j]) ? sqrtf(d2) : v2;
                    if (v < vmin[j]) {
                        s[j] = s[j] * __expf(alpha * (vmin[j] - v)) + 1.f;
                        vmin[j] = v;
                        thr[j] = v + margin;
                    } else {
                        s[j] += __expf(alpha * (v - vmin[j]));
                    }
                }
            }
        }
    } else {
        const float elo = 2.f / pf, ehi = 2.f * pf;
        for (int r = 0; r < ROWS_PER_CHUNK; r++) {
            float4 d4 = *(const float4*)(base + (size_t)r * M_TOT);
            float dv[4] = {d4.x, d4.y, d4.z, d4.w};
            float tt[4] = {tv.x, tv.y, tv.z, tv.w};
            #pragma unroll
            for (int j = 0; j < 4; j++) {
                float dd = sqrtf(dv[j]);
                float v = (dd < tt[j]) ? __powf(dd, elo) : __powf(dd, ehi);
                if (v < vmin[j]) {
                    s[j] = s[j] * __expf(alpha * (vmin[j] - v)) + 1.f;
                    vmin[j] = v;
                } else {
                    float a = alpha * (v - vmin[j]);
                    if (a > -30.f) s[j] += __expf(a);
                }
            }
        }
    }

    #pragma unroll
    for (int j = 0; j < 4; j++) {
        g_pmin[chunk * M_TOT + m + j] = vmin[j];
        g_psum[chunk * M_TOT + m + j] = s[j];
    }
}

// ---------------- kernel 6: combine partials -> lse per column ----------------
__global__ void combine_k(const float* __restrict__ lsig) {
    int m = blockIdx.x * 256 + threadIdx.x;
    float ls = lsig[0];
    float alpha = -0.5f * __expf(-2.f * ls);
    float vmin = 3.0e38f;
    #pragma unroll 8
    for (int c = 0; c < NCHUNK; c++)
        vmin = fminf(vmin, g_pmin[c * M_TOT + m]);
    float s = 0.f;
    #pragma unroll 8
    for (int c = 0; c < NCHUNK; c++) {
        float a = alpha * (g_pmin[c * M_TOT + m] - vmin);
        s += g_psum[c * M_TOT + m] * __expf(a);
    }
    g_lse[m] = alpha * vmin + logf(s);
}

// ---------------- kernel 7: final reduction -> loss ----------------
__global__ void final_k(const float* __restrict__ lsig, float* __restrict__ out) {
    __shared__ double red[256];
    double a = 0.0;
    for (int i = threadIdx.x; i < M_TOT; i += 256) a += (double)g_lse[i];
    red[threadIdx.x] = a;
    __syncthreads();
    for (int st = 128; st > 0; st >>= 1) {
        if (threadIdx.x < st) red[threadIdx.x] += red[threadIdx.x + st];
        __syncthreads();
    }
    if (threadIdx.x == 0) {
        double ls = (double)lsig[0];
        out[0] = (float)(-(red[0] / (double)M_TOT) + (double)KDIM * ls);
    }
}

// ---------------- launch ----------------
extern "C" void kernel_launch(void* const* d_in, const int* in_sizes, int n_in,
                              void* d_out, int out_size) {
    const float* z      = (const float*)d_in[0];
    const float* e      = (const float*)d_in[1];
    const float* belong = (const float*)d_in[2];
    const float* lsig   = (const float*)d_in[3];
    const float* maxd   = (const float*)d_in[4];
    const int*   pptr   = (n_in > 5) ? (const int*)d_in[5] : nullptr;
    (void)in_sizes; (void)out_size;

    const int smem_bytes = (2 * 128 * SPAD + 256) * 4;   // 70656
    cudaFuncSetAttribute(gemm_pass1, cudaFuncAttributeMaxDynamicSharedMemorySize,
                         smem_bytes);

    prep_zf<<<4096, 256>>>(z);
    prep_norms<<<64, 256>>>(e);
    gemm_pass1<<<dim3(M_TOT / 128, N_TOT / 128), 256, smem_bytes>>>(e, belong);
    newmax_k<<<M_TOT / 256, 256>>>(maxd);
    pass2<<<dim3(4, NCHUNK), 256>>>(lsig, pptr, pptr ? 1 : 0);
    combine_k<<<M_TOT / 256, 256>>>(lsig);
    final_k<<<1, 256>>>(lsig, (float*)d_out);
}

// round 4
// speedup vs baseline: 1.1795x; 1.0352x over previous
#include <cuda_runtime.h>
#include <cstdint>
#include <cstddef>

// ---------------- problem constants ----------------
#define N_TOT 16384      // B*H*W = 16*32*32
#define M_TOT 4096
#define KDIM  64
#define NTILES 128       // N_TOT / 128
#define MTILES 32        // M_TOT / 128

// ---------------- device scratch ----------------
__device__ float    g_zsq[N_TOT];
__device__ float    g_esq[M_TOT];
__device__ unsigned g_wmax[M_TOT];
__device__ float    g_t[M_TOT];
__device__ float    g_t2[M_TOT];
__device__ float    g_pmin[NTILES * M_TOT];   // per-(ntile,col) dmin (d2-space)
__device__ float    g_psum[NTILES * M_TOT];   // per-(ntile,col) rescaled sums
__device__ float    g_lse[M_TOT];
__device__ int      g_flags[M_TOT];
__device__ int      g_flagcnt;

// ---------------- helpers ----------------
__device__ __forceinline__ unsigned f2tf32(float x) {
    unsigned r;
    asm("cvt.rna.tf32.f32 %0, %1;" : "=r"(r) : "f"(x));
    return r;
}

__device__ __forceinline__ void mma_tf32(float c[4], const unsigned a[4], const unsigned b[2]) {
    asm volatile(
        "mma.sync.aligned.m16n8k8.row.col.f32.tf32.tf32.f32 "
        "{%0,%1,%2,%3}, {%4,%5,%6,%7}, {%8,%9}, {%0,%1,%2,%3};"
        : "+f"(c[0]), "+f"(c[1]), "+f"(c[2]), "+f"(c[3])
        : "r"(a[0]), "r"(a[1]), "r"(a[2]), "r"(a[3]),
          "r"(b[0]), "r"(b[1]));
}

// p-generalized "above-branch" value function: v(d2) = d2^p  (p=2 -> d2*d2)
__device__ __forceinline__ float vfun(float d2, bool fast, float pf) {
    return fast ? d2 * d2 : __powf(d2, pf);
}

__device__ __forceinline__ void get_alpha_p(const float* lsig, const int* pptr,
                                            int has_p, float& alpha, float& pf,
                                            bool& fast) {
    float ls = lsig[0];
    alpha = -0.5f * __expf(-2.f * ls);   // < 0
    int praw = has_p ? *pptr : 2;
    pf = (praw > 0 && praw < 1000) ? (float)praw : __int_as_float(praw);
    fast = (pf == 2.0f);
}

// ---------------- kernel 1: norms + resets ----------------
__global__ void prep_norms(const float* __restrict__ z, const float* __restrict__ e) {
    int i = blockIdx.x * 256 + threadIdx.x;        // grid covers N_TOT
    {   // zsq directly from z: z[b][c][hw], coalesced per-k iteration
        int b = i >> 10, hw = i & 1023;
        const float* zp = z + (size_t)b * 65536 + hw;
        float a0 = 0.f, a1 = 0.f, a2 = 0.f, a3 = 0.f;
        #pragma unroll
        for (int k = 0; k < 64; k += 4) {
            float v0 = zp[(k + 0) * 1024];
            float v1 = zp[(k + 1) * 1024];
            float v2 = zp[(k + 2) * 1024];
            float v3 = zp[(k + 3) * 1024];
            a0 += v0 * v0; a1 += v1 * v1; a2 += v2 * v2; a3 += v3 * v3;
        }
        g_zsq[i] = (a0 + a1) + (a2 + a3);
    }
    if (i < M_TOT) {
        const float4* p = (const float4*)(e + (size_t)i * KDIM);
        float a0 = 0.f, a1 = 0.f, a2 = 0.f, a3 = 0.f;
        #pragma unroll
        for (int k = 0; k < 16; k++) {
            float4 v = p[k];
            a0 += v.x * v.x; a1 += v.y * v.y; a2 += v.z * v.z; a3 += v.w * v.w;
        }
        g_esq[i] = (a0 + a1) + (a2 + a3);
        g_wmax[i] = 0u;
    }
    if (i == 0) g_flagcnt = 0;
}

// ---------------- kernel 2: fused tf32 GEMM + wmax + lse partials ----------------
// Tile 128(n) x 128(m), 256 threads, K=64 in one shot.
// A smem layout: [k][row], pitch 136 (conflict-free stage + frag loads)
// B smem layout: [row][k], pitch 68 (as R2)
#define APITCH 136
#define BPITCH 68
#define SM_FLOATS (64 * APITCH + 128 * BPITCH + 256)   // 17664 -> 70656 B

__global__ __launch_bounds__(256) void gemm_fused(const float* __restrict__ z,
                                                  const float* __restrict__ e,
                                                  const float* __restrict__ belong,
                                                  const float* __restrict__ lsig,
                                                  const int* __restrict__ pptr,
                                                  int has_p) {
    extern __shared__ float smf[];
    unsigned* As = (unsigned*)smf;                     // [64][136]
    unsigned* Bs = (unsigned*)(smf + 64 * APITCH);     // [128][68]
    float* szsq = smf + 64 * APITCH + 128 * BPITCH;    // 128
    float* sesq = szsq + 128;                          // 128
    // merge buffers alias the A-tile region (free after the k-loop)
    float* sMD = smf;            // [2][128]
    float* sMS = smf + 256;      // [2][128]
    float* sMW = smf + 512;      // [2][128]

    const int tid = threadIdx.x;
    const int m0 = blockIdx.x * 128;
    const int n0 = blockIdx.y * 128;
    const int ntile = blockIdx.y;

    float alpha, pf; bool fast;
    get_alpha_p(lsig, pptr, has_p, alpha, pf, fast);
    const float margin = -30.f / alpha;                // v-space contribution cutoff

    // ---- stage A from z (coalesced: consecutive tid -> consecutive row) ----
    const float* zb = z + (size_t)(n0 >> 10) * 65536 + (n0 & 1023);
    #pragma unroll
    for (int it = 0; it < 32; it++) {
        int idx = tid + it * 256;          // 0..8191
        int row = idx & 127, c = idx >> 7; // c = k index 0..63
        As[c * APITCH + row] = f2tf32(zb[c * 1024 + row]);
    }
    // ---- stage B from e (float4) ----
    #pragma unroll
    for (int it = 0; it < 8; it++) {
        int idx = tid + it * 256;          // 0..2047 float4 slots
        int row = idx >> 4, c4 = idx & 15;
        float4 v = *(const float4*)(e + (size_t)(m0 + row) * KDIM + c4 * 4);
        uint4 u = make_uint4(f2tf32(v.x), f2tf32(v.y), f2tf32(v.z), f2tf32(v.w));
        *(uint4*)(Bs + row * BPITCH + c4 * 4) = u;
    }
    if (tid < 128) {
        szsq[tid] = g_zsq[n0 + tid];
        sesq[tid] = g_esq[m0 + tid];
    }
    __syncthreads();

    const int lane = tid & 31, wid = tid >> 5;
    const int wm = wid >> 2;       // 0..1 (n halves)
    const int wn = wid & 3;        // 0..3 (m quarters)
    const int ar = lane >> 2, ac = lane & 3;

    float acc[4][4][4];
    #pragma unroll
    for (int i = 0; i < 4; i++)
        #pragma unroll
        for (int j = 0; j < 4; j++)
            #pragma unroll
            for (int r = 0; r < 4; r++) acc[i][j][r] = 0.f;

    #pragma unroll
    for (int ks = 0; ks < 8; ks++) {
        const int k0 = ks * 8;
        unsigned a[4][4], b[4][2];
        #pragma unroll
        for (int i = 0; i < 4; i++) {
            int rb = wm * 64 + i * 16 + ar;
            a[i][0] = As[(k0 + ac) * APITCH + rb];
            a[i][1] = As[(k0 + ac) * APITCH + rb + 8];
            a[i][2] = As[(k0 + ac + 4) * APITCH + rb];
            a[i][3] = As[(k0 + ac + 4) * APITCH + rb + 8];
        }
        #pragma unroll
        for (int j = 0; j < 4; j++) {
            int cb = wn * 32 + j * 8 + ar;
            b[j][0] = Bs[cb * BPITCH + k0 + ac];
            b[j][1] = Bs[cb * BPITCH + k0 + ac + 4];
        }
        #pragma unroll
        for (int i = 0; i < 4; i++)
            #pragma unroll
            for (int j = 0; j < 4; j++)
                mma_tf32(acc[i][j], a[i], b[j]);
    }

    // ---- fused epilogue: d2, wmax, online lse (above-branch assumption) ----
    float dmin_[4][2], s_[4][2], dthr_[4][2], wloc[4][2];
    #pragma unroll
    for (int j = 0; j < 4; j++)
        #pragma unroll
        for (int p_ = 0; p_ < 2; p_++) {
            dmin_[j][p_] = 1e19f; s_[j][p_] = 0.f;
            dthr_[j][p_] = 3.0e38f; wloc[j][p_] = 0.f;
        }

    float esv[4][2], zsv[4][2];
    #pragma unroll
    for (int j = 0; j < 4; j++) {
        int lc = wn * 32 + j * 8 + 2 * ac;
        esv[j][0] = sesq[lc];
        esv[j][1] = sesq[lc + 1];
    }
    #pragma unroll
    for (int i = 0; i < 4; i++) {
        int lr0 = wm * 64 + i * 16 + ar;
        zsv[i][0] = szsq[lr0];
        zsv[i][1] = szsq[lr0 + 8];
    }

    #pragma unroll
    for (int i = 0; i < 4; i++) {
        int lr0 = wm * 64 + i * 16 + ar;
        size_t gr0 = (size_t)(n0 + lr0) * M_TOT;
        size_t gr1 = (size_t)(n0 + lr0 + 8) * M_TOT;
        float zs0 = zsv[i][0], zs1 = zsv[i][1];
        #pragma unroll
        for (int j = 0; j < 4; j++) {
            int gc = m0 + wn * 32 + j * 8 + 2 * ac;
            float es0 = esv[j][0], es1 = esv[j][1];
            float d00 = fmaxf(zs0 + es0 - 2.f * acc[i][j][0], 0.f);
            float d01 = fmaxf(zs0 + es1 - 2.f * acc[i][j][1], 0.f);
            float d10 = fmaxf(zs1 + es0 - 2.f * acc[i][j][2], 0.f);
            float d11 = fmaxf(zs1 + es1 - 2.f * acc[i][j][3], 0.f);

            float2 b0 = *(const float2*)(belong + gr0 + gc);
            float2 b1 = *(const float2*)(belong + gr1 + gc);
            wloc[j][0] = fmaxf(wloc[j][0], fmaxf(b0.x * b0.x * d00, b1.x * b1.x * d10));
            wloc[j][1] = fmaxf(wloc[j][1], fmaxf(b0.y * b0.y * d01, b1.y * b1.y * d11));

            // online lse in d2-space, v = d2^p assumed
            #pragma unroll
            for (int p_ = 0; p_ < 2; p_++) {
                float da = (p_ == 0) ? d00 : d01;
                float db = (p_ == 0) ? d10 : d11;
                #pragma unroll
                for (int hh = 0; hh < 2; hh++) {
                    float d2 = (hh == 0) ? da : db;
                    if (__builtin_expect(d2 < dthr_[j][p_], 0)) {
                        if (d2 < dmin_[j][p_]) {
                            float vold = vfun(dmin_[j][p_], fast, pf);
                            float vnew = vfun(d2, fast, pf);
                            s_[j][p_] = s_[j][p_] * __expf(alpha * (vold - vnew)) + 1.f;
                            dmin_[j][p_] = d2;
                            float vlim = vnew + margin;
                            dthr_[j][p_] = fast ? sqrtf(vlim) : __powf(vlim, 1.f / pf);
                        } else {
                            float v = vfun(d2, fast, pf);
                            float vm = vfun(dmin_[j][p_], fast, pf);
                            s_[j][p_] += __expf(alpha * (v - vm));
                        }
                    }
                }
            }
        }
    }

    // ---- warp butterfly over ar-lanes (xor 4,8,16): min(dmin), sum(s), max(w) ----
    float fdm[4][2], fs[4][2], fw[4][2];
    #pragma unroll
    for (int j = 0; j < 4; j++)
        #pragma unroll
        for (int p_ = 0; p_ < 2; p_++) {
            float dm = dmin_[j][p_];
            #pragma unroll
            for (int off = 4; off < 32; off <<= 1)
                dm = fminf(dm, __shfl_xor_sync(0xffffffffu, dm, off));
            float sv = s_[j][p_] *
                __expf(alpha * (vfun(dmin_[j][p_], fast, pf) - vfun(dm, fast, pf)));
            #pragma unroll
            for (int off = 4; off < 32; off <<= 1)
                sv += __shfl_xor_sync(0xffffffffu, sv, off);
            float wv = wloc[j][p_];
            #pragma unroll
            for (int off = 4; off < 32; off <<= 1)
                wv = fmaxf(wv, __shfl_xor_sync(0xffffffffu, wv, off));
            fdm[j][p_] = dm; fs[j][p_] = sv; fw[j][p_] = wv;
        }

    __syncthreads();   // A-tile reads done; safe to alias merge buffers
    if (lane < 4) {
        #pragma unroll
        for (int j = 0; j < 4; j++)
            #pragma unroll
            for (int p_ = 0; p_ < 2; p_++) {
                int col = wn * 32 + j * 8 + 2 * lane + p_;
                sMD[wm * 128 + col] = fdm[j][p_];
                sMS[wm * 128 + col] = fs[j][p_];
                sMW[wm * 128 + col] = fw[j][p_];
            }
    }
    __syncthreads();

    if (tid < 128) {
        int col = tid;
        float d0 = sMD[col], d1 = sMD[128 + col];
        float dm = fminf(d0, d1);
        float vm = vfun(dm, fast, pf);
        float s = sMS[col] * __expf(alpha * (vfun(d0, fast, pf) - vm))
                + sMS[128 + col] * __expf(alpha * (vfun(d1, fast, pf) - vm));
        g_pmin[ntile * M_TOT + m0 + col] = dm;
        g_psum[ntile * M_TOT + m0 + col] = s;
        atomicMax(&g_wmax[m0 + col],
                  __float_as_uint(fmaxf(sMW[col], sMW[128 + col])));
    }
}

// ---------------- kernel 3: EMA new_max ----------------
__global__ void newmax_k(const float* __restrict__ maxd) {
    int i = blockIdx.x * 256 + threadIdx.x;
    float bm = sqrtf(__uint_as_float(g_wmax[i]));
    float nm = fmaxf(0.999f * maxd[i] + 0.001f * bm, 1e-8f);
    g_t[i] = nm;
    g_t2[i] = nm * nm;
}

// ---------------- kernel 4: combine tiles -> lse; flag branch-violating cols ----
__global__ void finalize_k(const float* __restrict__ lsig,
                           const int* __restrict__ pptr, int has_p) {
    int col = blockIdx.x * 256 + threadIdx.x;
    float alpha, pf; bool fast;
    get_alpha_p(lsig, pptr, has_p, alpha, pf, fast);

    float dmc = 3.0e38f;
    #pragma unroll 8
    for (int t = 0; t < NTILES; t++)
        dmc = fminf(dmc, g_pmin[t * M_TOT + col]);
    float vm = vfun(dmc, fast, pf);
    float s = 0.f;
    #pragma unroll 8
    for (int t = 0; t < NTILES; t++)
        s += g_psum[t * M_TOT + col] *
             __expf(alpha * (vfun(g_pmin[t * M_TOT + col], fast, pf) - vm));
    g_lse[col] = alpha * vm + logf(s);

    if (dmc < g_t2[col]) {                 // some element takes the sqrt branch
        int idx = atomicAdd(&g_flagcnt, 1);
        g_flags[idx] = col;
    }
}

// ---------------- kernel 5: exact recompute for flagged columns (rare) -------
__global__ void fixup_k(const float* __restrict__ z, const float* __restrict__ e,
                        const float* __restrict__ lsig,
                        const int* __restrict__ pptr, int has_p) {
    __shared__ float esm[64];
    __shared__ float red_v[256];
    __shared__ float red_s[256];
    const int tid = threadIdx.x;
    const int cnt = g_flagcnt;
    float alpha, pf; bool fast;
    get_alpha_p(lsig, pptr, has_p, alpha, pf, fast);
    const float elo = 2.f / pf, ehi = 2.f * pf;

    for (int f = blockIdx.x; f < cnt; f += gridDim.x) {
        int col = g_flags[f];
        if (tid < 64) esm[tid] = e[col * 64 + tid];
        __syncthreads();
        float t = g_t[col];
        float esq = g_esq[col];
        float vmin = 3.0e38f, s = 0.f;
        for (int n = tid; n < N_TOT; n += 256) {
            const float* zp = z + (size_t)(n >> 10) * 65536 + (n & 1023);
            float dot = 0.f;
            #pragma unroll
            for (int k = 0; k < 64; k++) dot += zp[k * 1024] * esm[k];
            float d2 = fmaxf(g_zsq[n] + esq - 2.f * dot, 0.f);
            float dist = sqrtf(d2);
            float v;
            if (fast) v = (dist < t) ? dist : d2 * d2;
            else      v = (dist < t) ? __powf(dist, elo) : __powf(dist, ehi);
            if (v < vmin) {
                s = s * __expf(alpha * (vmin - v)) + 1.f;
                vmin = v;
            } else {
                float a1 = alpha * (v - vmin);
                if (a1 > -30.f) s += __expf(a1);
            }
        }
        red_v[tid] = vmin; red_s[tid] = s;
        __syncthreads();
        if (tid == 0) {
            float vm = 3.0e38f;
            for (int i = 0; i < 256; i++) vm = fminf(vm, red_v[i]);
            float ss = 0.f;
            for (int i = 0; i < 256; i++)
                ss += red_s[i] * __expf(alpha * (red_v[i] - vm));
            g_lse[col] = alpha * vm + logf(ss);
        }
        __syncthreads();
    }
}

// ---------------- kernel 6: final reduction -> loss ----------------
__global__ void final_k(const float* __restrict__ lsig, float* __restrict__ out) {
    __shared__ double red[256];
    double a = 0.0;
    for (int i = threadIdx.x; i < M_TOT; i += 256) a += (double)g_lse[i];
    red[threadIdx.x] = a;
    __syncthreads();
    for (int st = 128; st > 0; st >>= 1) {
        if (threadIdx.x < st) red[threadIdx.x] += red[threadIdx.x + st];
        __syncthreads();
    }
    if (threadIdx.x == 0) {
        double ls = (double)lsig[0];
        out[0] = (float)(-(red[0] / (double)M_TOT) + (double)KDIM * ls);
    }
}

// ---------------- launch ----------------
extern "C" void kernel_launch(void* const* d_in, const int* in_sizes, int n_in,
                              void* d_out, int out_size) {
    const float* z      = (const float*)d_in[0];
    const float* e      = (const float*)d_in[1];
    const float* belong = (const float*)d_in[2];
    const float* lsig   = (const float*)d_in[3];
    const float* maxd   = (const float*)d_in[4];
    const int*   pptr   = (n_in > 5) ? (const int*)d_in[5] : nullptr;
    (void)in_sizes; (void)out_size;
    int has_p = pptr ? 1 : 0;

    const int smem_bytes = SM_FLOATS * 4;   // 70656
    cudaFuncSetAttribute(gemm_fused, cudaFuncAttributeMaxDynamicSharedMemorySize,
                         smem_bytes);

    prep_norms<<<N_TOT / 256, 256>>>(z, e);
    gemm_fused<<<dim3(MTILES, NTILES), 256, smem_bytes>>>(z, e, belong, lsig,
                                                          pptr, has_p);
    newmax_k<<<M_TOT / 256, 256>>>(maxd);
    finalize_k<<<M_TOT / 256, 256>>>(lsig, pptr, has_p);
    fixup_k<<<64, 256>>>(z, e, lsig, pptr, has_p);
    final_k<<<1, 256>>>(lsig, (float*)d_out);
}

// round 5
// speedup vs baseline: 1.3383x; 1.1346x over previous
#include <cuda_runtime.h>
#include <cuda_fp16.h>
#include <cstdint>
#include <cstddef>

// ---------------- problem constants ----------------
#define N_TOT 16384      // B*H*W = 16*32*32
#define M_TOT 4096
#define KDIM  64
#define NTILES 128       // N_TOT / 128
#define MTILES 32        // M_TOT / 128

// ---------------- device scratch ----------------
__device__ float    g_zsq[N_TOT];
__device__ float    g_esq[M_TOT];
__device__ unsigned g_wmax[M_TOT];
__device__ float    g_t[M_TOT];
__device__ float    g_t2[M_TOT];
__device__ float    g_pmin[NTILES * M_TOT];   // per-(ntile,col) dmin (d2-space)
__device__ float    g_psum[NTILES * M_TOT];   // per-(ntile,col) rescaled sums
__device__ float    g_lse[M_TOT];
__device__ int      g_flags[M_TOT];
__device__ int      g_flagcnt;

// ---------------- helpers ----------------
__device__ __forceinline__ uint32_t s2u(const void* p) {
    return (uint32_t)__cvta_generic_to_shared(p);
}

__device__ __forceinline__ void ldsm4(uint32_t& r0, uint32_t& r1, uint32_t& r2,
                                      uint32_t& r3, uint32_t addr) {
    asm volatile("ldmatrix.sync.aligned.m8n8.x4.shared.b16 {%0,%1,%2,%3}, [%4];"
                 : "=r"(r0), "=r"(r1), "=r"(r2), "=r"(r3) : "r"(addr));
}

__device__ __forceinline__ void mma_f16(float c[4], const uint32_t a[4],
                                        uint32_t b0, uint32_t b1) {
    asm volatile(
        "mma.sync.aligned.m16n8k16.row.col.f32.f16.f16.f32 "
        "{%0,%1,%2,%3}, {%4,%5,%6,%7}, {%8,%9}, {%0,%1,%2,%3};"
        : "+f"(c[0]), "+f"(c[1]), "+f"(c[2]), "+f"(c[3])
        : "r"(a[0]), "r"(a[1]), "r"(a[2]), "r"(a[3]), "r"(b0), "r"(b1));
}

// p-generalized "above-branch" value function: v(d2) = d2^p  (p=2 -> d2*d2)
__device__ __forceinline__ float vfun(float d2, bool fast, float pf) {
    return fast ? d2 * d2 : __powf(d2, pf);
}

__device__ __forceinline__ void get_alpha_p(const float* lsig, const int* pptr,
                                            int has_p, float& alpha, float& pf,
                                            bool& fast) {
    float ls = lsig[0];
    alpha = -0.5f * __expf(-2.f * ls);   // < 0
    int praw = has_p ? *pptr : 2;
    pf = (praw > 0 && praw < 1000) ? (float)praw : __int_as_float(praw);
    fast = (pf == 2.0f);
}

// ---------------- kernel 1: norms + resets ----------------
__global__ void prep_norms(const float* __restrict__ z, const float* __restrict__ e) {
    int i = blockIdx.x * 256 + threadIdx.x;        // grid covers N_TOT
    {   // zsq directly from z: z[b][c][hw], coalesced per-k iteration
        int b = i >> 10, hw = i & 1023;
        const float* zp = z + (size_t)b * 65536 + hw;
        float a0 = 0.f, a1 = 0.f, a2 = 0.f, a3 = 0.f;
        #pragma unroll
        for (int k = 0; k < 64; k += 4) {
            float v0 = zp[(k + 0) * 1024];
            float v1 = zp[(k + 1) * 1024];
            float v2 = zp[(k + 2) * 1024];
            float v3 = zp[(k + 3) * 1024];
            a0 += v0 * v0; a1 += v1 * v1; a2 += v2 * v2; a3 += v3 * v3;
        }
        g_zsq[i] = (a0 + a1) + (a2 + a3);
    }
    if (i < M_TOT) {
        const float4* p = (const float4*)(e + (size_t)i * KDIM);
        float a0 = 0.f, a1 = 0.f, a2 = 0.f, a3 = 0.f;
        #pragma unroll
        for (int k = 0; k < 16; k++) {
            float4 v = p[k];
            a0 += v.x * v.x; a1 += v.y * v.y; a2 += v.z * v.z; a3 += v.w * v.w;
        }
        g_esq[i] = (a0 + a1) + (a2 + a3);
        g_wmax[i] = 0u;
    }
    if (i == 0) g_flagcnt = 0;
}

// ---------------- kernel 2: fused fp16 GEMM + wmax + lse partials ----------------
// Tile 128(n) x 128(m), 256 threads, K=64 in 4 k16 steps.
// A/B half tiles: [row][k], pitch 72 halves (144 B) -> conflict-free LDSM rows.
// A holds -2*z so acc = -2*dot; d2 = zsq + esq + acc.
#define HPITCH_B 144                         // bytes per half-tile row
#define SM_A    0                            // 128*144 = 18432
#define SM_B    18432                        // 18432
#define SM_ZSQ  36864                        // 512
#define SM_ESQ  37376                        // 512
#define SM_MRG  37888                        // 3 * 1024
#define SMEM_BYTES 40960

__global__ __launch_bounds__(256, 2) void gemm_fused(const float* __restrict__ z,
                                                     const float* __restrict__ e,
                                                     const float* __restrict__ belong,
                                                     const float* __restrict__ lsig,
                                                     const int* __restrict__ pptr,
                                                     int has_p) {
    __shared__ __align__(16) unsigned char smraw[SMEM_BYTES];
    const uint32_t smb = s2u(smraw);

    const int tid = threadIdx.x;
    const int m0 = blockIdx.x * 128;
    const int n0 = blockIdx.y * 128;
    const int ntile = blockIdx.y;
    const int lane = tid & 31, wid = tid >> 5;

    float alpha, pf; bool fast;
    get_alpha_p(lsig, pptr, has_p, alpha, pf, fast);
    const float margin = -30.f / alpha;                // v-space contribution cutoff

    // ---- stage A = -2*z as half, layout [row][k] (STS banks 4*ar+kq: distinct) ----
    {
        const float* zb = z + (size_t)(n0 >> 10) * 65536 + (n0 & 1023);
        int ar = lane & 7, kq = lane >> 3;             // 8 rows x 4 kpairs per warp
        #pragma unroll
        for (int it = 0; it < 16; it++) {
            int g = (tid >> 5) + it * 8;               // 0..127
            int rb = g & 15, kb = g >> 4;              // 16 rowblocks, 8 kblocks
            int row = rb * 8 + ar;
            int k = (kb * 4 + kq) * 2;
            float v0 = zb[(k + 0) * 1024 + row];
            float v1 = zb[(k + 1) * 1024 + row];
            __half2 h = __floats2half2_rn(-2.f * v0, -2.f * v1);
            *(__half2*)(smraw + SM_A + row * HPITCH_B + k * 2) = h;
        }
    }
    // ---- stage B = e as half ----
    #pragma unroll
    for (int it = 0; it < 8; it++) {
        int idx = tid + it * 256;                      // 0..2047
        int row = idx >> 4, c4 = idx & 15;
        float4 v = *(const float4*)(e + (size_t)(m0 + row) * KDIM + c4 * 4);
        __half2 h01 = __floats2half2_rn(v.x, v.y);
        __half2 h23 = __floats2half2_rn(v.z, v.w);
        uint2 u = make_uint2(*(uint32_t*)&h01, *(uint32_t*)&h23);
        *(uint2*)(smraw + SM_B + row * HPITCH_B + c4 * 8) = u;
    }
    float* szsq = (float*)(smraw + SM_ZSQ);
    float* sesq = (float*)(smraw + SM_ESQ);
    if (tid < 128) {
        szsq[tid] = g_zsq[n0 + tid];
        sesq[tid] = g_esq[m0 + tid];
    }
    __syncthreads();

    const int wm = wid >> 2;       // 0..1 (n halves)
    const int wn = wid & 3;        // 0..3 (m quarters)
    const int ar = lane >> 2, ac = lane & 3;

    float acc[4][4][4];
    #pragma unroll
    for (int i = 0; i < 4; i++)
        #pragma unroll
        for (int j = 0; j < 4; j++)
            #pragma unroll
            for (int r = 0; r < 4; r++) acc[i][j][r] = 0.f;

    // ldmatrix lane addressing
    const uint32_t a_base = smb + SM_A +
        (uint32_t)((wm * 64 + (lane & 7) + ((lane >> 3) & 1) * 8) * HPITCH_B) +
        ((lane >> 4) & 1) * 16;
    const uint32_t b_base = smb + SM_B +
        (uint32_t)((wn * 32 + (lane & 7) + ((lane >> 3) & 1) * 8) * HPITCH_B) +
        ((lane >> 4) & 1) * 16;

    #pragma unroll
    for (int ks = 0; ks < 4; ks++) {
        uint32_t a[4][4], b[4][2];
        #pragma unroll
        for (int i = 0; i < 4; i++)
            ldsm4(a[i][0], a[i][1], a[i][2], a[i][3],
                  a_base + i * 16 * HPITCH_B + ks * 32);
        ldsm4(b[0][0], b[1][0], b[0][1], b[1][1], b_base + ks * 32);
        ldsm4(b[2][0], b[3][0], b[2][1], b[3][1],
              b_base + 16 * HPITCH_B + ks * 32);
        #pragma unroll
        for (int i = 0; i < 4; i++)
            #pragma unroll
            for (int j = 0; j < 4; j++)
                mma_f16(acc[i][j], a[i], b[j][0], b[j][1]);
    }

    // ---- fused epilogue: d2 = zs + es + acc (no clamp; flags cover negatives) ----
    float dmin_[4][2], s_[4][2], dthr_[4][2], wloc[4][2];
    #pragma unroll
    for (int j = 0; j < 4; j++)
        #pragma unroll
        for (int p_ = 0; p_ < 2; p_++) {
            dmin_[j][p_] = 1e19f; s_[j][p_] = 0.f;
            dthr_[j][p_] = 3.0e38f; wloc[j][p_] = 0.f;
        }

    float esv[4][2], zsv[4][2];
    #pragma unroll
    for (int j = 0; j < 4; j++) {
        int lc = wn * 32 + j * 8 + 2 * ac;
        esv[j][0] = sesq[lc];
        esv[j][1] = sesq[lc + 1];
    }
    #pragma unroll
    for (int i = 0; i < 4; i++) {
        int lr0 = wm * 64 + i * 16 + ar;
        zsv[i][0] = szsq[lr0];
        zsv[i][1] = szsq[lr0 + 8];
    }

    #pragma unroll
    for (int i = 0; i < 4; i++) {
        int lr0 = wm * 64 + i * 16 + ar;
        size_t gr0 = (size_t)(n0 + lr0) * M_TOT;
        size_t gr1 = (size_t)(n0 + lr0 + 8) * M_TOT;
        float zs0 = zsv[i][0], zs1 = zsv[i][1];
        #pragma unroll
        for (int j = 0; j < 4; j++) {
            int gc = m0 + wn * 32 + j * 8 + 2 * ac;
            float es0 = esv[j][0], es1 = esv[j][1];
            float d00 = (zs0 + es0) + acc[i][j][0];
            float d01 = (zs0 + es1) + acc[i][j][1];
            float d10 = (zs1 + es0) + acc[i][j][2];
            float d11 = (zs1 + es1) + acc[i][j][3];

            float2 b0 = *(const float2*)(belong + gr0 + gc);
            float2 b1 = *(const float2*)(belong + gr1 + gc);
            wloc[j][0] = fmaxf(wloc[j][0], fmaxf(b0.x * b0.x * d00, b1.x * b1.x * d10));
            wloc[j][1] = fmaxf(wloc[j][1], fmaxf(b0.y * b0.y * d01, b1.y * b1.y * d11));

            // online lse in d2-space, v = d2^p assumed (above-branch)
            #pragma unroll
            for (int p_ = 0; p_ < 2; p_++) {
                float da = (p_ == 0) ? d00 : d01;
                float db = (p_ == 0) ? d10 : d11;
                #pragma unroll
                for (int hh = 0; hh < 2; hh++) {
                    float d2 = (hh == 0) ? da : db;
                    if (__builtin_expect(d2 < dthr_[j][p_], 0)) {
                        if (d2 < dmin_[j][p_]) {
                            float vold = vfun(dmin_[j][p_], fast, pf);
                            float vnew = vfun(d2, fast, pf);
                            s_[j][p_] = s_[j][p_] * __expf(alpha * (vold - vnew)) + 1.f;
                            dmin_[j][p_] = d2;
                            float vlim = vnew + margin;
                            dthr_[j][p_] = fast ? sqrtf(vlim) : __powf(vlim, 1.f / pf);
                        } else {
                            float v = vfun(d2, fast, pf);
                            float vm = vfun(dmin_[j][p_], fast, pf);
                            s_[j][p_] += __expf(alpha * (v - vm));
                        }
                    }
                }
            }
        }
    }

    // ---- warp butterfly over ar-lanes (xor 4,8,16): min(dmin), sum(s), max(w) ----
    float fdm[4][2], fs[4][2], fw[4][2];
    #pragma unroll
    for (int j = 0; j < 4; j++)
        #pragma unroll
        for (int p_ = 0; p_ < 2; p_++) {
            float dm = dmin_[j][p_];
            #pragma unroll
            for (int off = 4; off < 32; off <<= 1)
                dm = fminf(dm, __shfl_xor_sync(0xffffffffu, dm, off));
            float sv = s_[j][p_] *
                __expf(alpha * (vfun(dmin_[j][p_], fast, pf) - vfun(dm, fast, pf)));
            #pragma unroll
            for (int off = 4; off < 32; off <<= 1)
                sv += __shfl_xor_sync(0xffffffffu, sv, off);
            float wv = wloc[j][p_];
            #pragma unroll
            for (int off = 4; off < 32; off <<= 1)
                wv = fmaxf(wv, __shfl_xor_sync(0xffffffffu, wv, off));
            fdm[j][p_] = dm; fs[j][p_] = sv; fw[j][p_] = wv;
        }

    float* sMD = (float*)(smraw + SM_MRG);
    float* sMS = sMD + 256;
    float* sMW = sMD + 512;
    if (lane < 4) {
        #pragma unroll
        for (int j = 0; j < 4; j++)
            #pragma unroll
            for (int p_ = 0; p_ < 2; p_++) {
                int col = wn * 32 + j * 8 + 2 * lane + p_;
                sMD[wm * 128 + col] = fdm[j][p_];
                sMS[wm * 128 + col] = fs[j][p_];
                sMW[wm * 128 + col] = fw[j][p_];
            }
    }
    __syncthreads();

    if (tid < 128) {
        int col = tid;
        float d0 = sMD[col], d1 = sMD[128 + col];
        float dm = fminf(d0, d1);
        float vm = vfun(dm, fast, pf);
        float s = sMS[col] * __expf(alpha * (vfun(d0, fast, pf) - vm))
                + sMS[128 + col] * __expf(alpha * (vfun(d1, fast, pf) - vm));
        g_pmin[ntile * M_TOT + m0 + col] = dm;
        g_psum[ntile * M_TOT + m0 + col] = s;
        atomicMax(&g_wmax[m0 + col],
                  __float_as_uint(fmaxf(sMW[col], sMW[128 + col])));
    }
}

// ---------------- kernel 3: newmax + combine tiles -> lse + flag ----------------
// grid 128 blocks x 256 threads: block handles 32 columns, 8 warps split 128 tiles.
__global__ void finalize_k(const float* __restrict__ maxd,
                           const float* __restrict__ lsig,
                           const int* __restrict__ pptr, int has_p) {
    __shared__ float s_t2[32];
    __shared__ float sdm[8][32];
    __shared__ float ssm[8][32];
    const int lane = threadIdx.x & 31;
    const int warp = threadIdx.x >> 5;
    const int col = blockIdx.x * 32 + lane;

    float alpha, pf; bool fast;
    get_alpha_p(lsig, pptr, has_p, alpha, pf, fast);

    if (threadIdx.x < 32) {   // EMA new_max for this block's 32 columns
        float bm = sqrtf(__uint_as_float(g_wmax[col]));
        float nm = fmaxf(0.999f * maxd[col] + 0.001f * bm, 1e-8f);
        g_t[col] = nm;
        g_t2[col] = nm * nm;
        s_t2[lane] = nm * nm;
    }

    float dmc = 3.0e38f, s = 0.f;
    #pragma unroll 4
    for (int t = warp * 16; t < warp * 16 + 16; t++) {
        float pm = g_pmin[t * M_TOT + col];
        float ps = g_psum[t * M_TOT + col];
        if (pm < dmc) {
            s = s * __expf(alpha * (vfun(dmc, fast, pf) - vfun(pm, fast, pf))) + ps;
            dmc = pm;
        } else {
            s += ps * __expf(alpha * (vfun(pm, fast, pf) - vfun(dmc, fast, pf)));
        }
    }
    sdm[warp][lane] = dmc;
    ssm[warp][lane] = s;
    __syncthreads();

    if (warp == 0) {
        float dall = 3.0e38f;
        #pragma unroll
        for (int w = 0; w < 8; w++) dall = fminf(dall, sdm[w][lane]);
        float vall = vfun(dall, fast, pf);
        float sall = 0.f;
        #pragma unroll
        for (int w = 0; w < 8; w++)
            sall += ssm[w][lane] * __expf(alpha * (vfun(sdm[w][lane], fast, pf) - vall));
        g_lse[col] = alpha * vall + logf(sall);
        if (dall < s_t2[lane]) {         // some element takes the below branch
            int idx = atomicAdd(&g_flagcnt, 1);
            g_flags[idx] = col;
        }
    }
}

// ---------------- kernel 4: exact recompute for flagged columns (rare) -------
__global__ void fixup_k(const float* __restrict__ z, const float* __restrict__ e,
                        const float* __restrict__ lsig,
                        const int* __restrict__ pptr, int has_p) {
    __shared__ float esm[64];
    __shared__ float red_v[256];
    __shared__ float red_s[256];
    const int tid = threadIdx.x;
    const int cnt = g_flagcnt;
    float alpha, pf; bool fast;
    get_alpha_p(lsig, pptr, has_p, alpha, pf, fast);
    const float elo = 2.f / pf, ehi = 2.f * pf;

    for (int f = blockIdx.x; f < cnt; f += gridDim.x) {
        int col = g_flags[f];
        if (tid < 64) esm[tid] = e[col * 64 + tid];
        __syncthreads();
        float t = g_t[col];
        float esq = g_esq[col];
        float vmin = 3.0e38f, s = 0.f;
        for (int n = tid; n < N_TOT; n += 256) {
            const float* zp = z + (size_t)(n >> 10) * 65536 + (n & 1023);
            float dot = 0.f;
            #pragma unroll
            for (int k = 0; k < 64; k++) dot += zp[k * 1024] * esm[k];
            float d2 = fmaxf(g_zsq[n] + esq - 2.f * dot, 0.f);
            float dist = sqrtf(d2);
            float v;
            if (fast) v = (dist < t) ? dist : d2 * d2;
            else      v = (dist < t) ? __powf(dist, elo) : __powf(dist, ehi);
            if (v < vmin) {
                s = s * __expf(alpha * (vmin - v)) + 1.f;
                vmin = v;
            } else {
                float a1 = alpha * (v - vmin);
                if (a1 > -30.f) s += __expf(a1);
            }
        }
        red_v[tid] = vmin; red_s[tid] = s;
        __syncthreads();
        if (tid == 0) {
            float vm = 3.0e38f;
            for (int i = 0; i < 256; i++) vm = fminf(vm, red_v[i]);
            float ss = 0.f;
            for (int i = 0; i < 256; i++)
                ss += red_s[i] * __expf(alpha * (red_v[i] - vm));
            g_lse[col] = alpha * vm + logf(ss);
        }
        __syncthreads();
    }
}

// ---------------- kernel 5: final reduction -> loss ----------------
__global__ void final_k(const float* __restrict__ lsig, float* __restrict__ out) {
    __shared__ double red[256];
    double a = 0.0;
    for (int i = threadIdx.x; i < M_TOT; i += 256) a += (double)g_lse[i];
    red[threadIdx.x] = a;
    __syncthreads();
    for (int st = 128; st > 0; st >>= 1) {
        if (threadIdx.x < st) red[threadIdx.x] += red[threadIdx.x + st];
        __syncthreads();
    }
    if (threadIdx.x == 0) {
        double ls = (double)lsig[0];
        out[0] = (float)(-(red[0] / (double)M_TOT) + (double)KDIM * ls);
    }
}

// ---------------- launch ----------------
extern "C" void kernel_launch(void* const* d_in, const int* in_sizes, int n_in,
                              void* d_out, int out_size) {
    const float* z      = (const float*)d_in[0];
    const float* e      = (const float*)d_in[1];
    const float* belong = (const float*)d_in[2];
    const float* lsig   = (const float*)d_in[3];
    const float* maxd   = (const float*)d_in[4];
    const int*   pptr   = (n_in > 5) ? (const int*)d_in[5] : nullptr;
    (void)in_sizes; (void)out_size;
    int has_p = pptr ? 1 : 0;

    prep_norms<<<N_TOT / 256, 256>>>(z, e);
    gemm_fused<<<dim3(MTILES, NTILES), 256>>>(z, e, belong, lsig, pptr, has_p);
    finalize_k<<<M_TOT / 32, 256>>>(maxd, lsig, pptr, has_p);
    fixup_k<<<64, 256>>>(z, e, lsig, pptr, has_p);
    final_k<<<1, 256>>>(lsig, (float*)d_out);
}

// round 6
// speedup vs baseline: 1.5107x; 1.1289x over previous
#include <cuda_runtime.h>
#include <cuda_fp16.h>
#include <cstdint>
#include <cstddef>

// ---------------- problem constants ----------------
#define N_TOT 16384      // B*H*W = 16*32*32
#define M_TOT 4096
#define KDIM  64
#define NTILES 128       // N_TOT / 128
#define MTILES 32        // M_TOT / 128

// ---------------- device scratch ----------------
__device__ float    g_zsq[N_TOT];
__device__ float    g_esq[M_TOT];
__device__ unsigned g_wmax[M_TOT];
__device__ float    g_t[M_TOT];
__device__ float    g_t2[M_TOT];
__device__ float    g_pmin[NTILES * M_TOT];   // per-(ntile,col) dmin (d2-space)
__device__ float    g_psum[NTILES * M_TOT];   // per-(ntile,col) rescaled sums
__device__ float    g_lse[M_TOT];
__device__ int      g_flags[M_TOT];
__device__ int      g_flagcnt;

// ---------------- helpers ----------------
__device__ __forceinline__ uint32_t s2u(const void* p) {
    return (uint32_t)__cvta_generic_to_shared(p);
}

__device__ __forceinline__ void ldsm4(uint32_t& r0, uint32_t& r1, uint32_t& r2,
                                      uint32_t& r3, uint32_t addr) {
    asm volatile("ldmatrix.sync.aligned.m8n8.x4.shared.b16 {%0,%1,%2,%3}, [%4];"
                 : "=r"(r0), "=r"(r1), "=r"(r2), "=r"(r3) : "r"(addr));
}

__device__ __forceinline__ void mma_f16(float c[4], const uint32_t a[4],
                                        uint32_t b0, uint32_t b1) {
    asm volatile(
        "mma.sync.aligned.m16n8k16.row.col.f32.f16.f16.f32 "
        "{%0,%1,%2,%3}, {%4,%5,%6,%7}, {%8,%9}, {%0,%1,%2,%3};"
        : "+f"(c[0]), "+f"(c[1]), "+f"(c[2]), "+f"(c[3])
        : "r"(a[0]), "r"(a[1]), "r"(a[2]), "r"(a[3]), "r"(b0), "r"(b1));
}

// p-generalized "above-branch" value function: v(d2) = d2^p  (p=2 -> d2*d2)
__device__ __forceinline__ float vfun(float d2, bool fast, float pf) {
    return fast ? d2 * d2 : __powf(d2, pf);
}

__device__ __forceinline__ void get_alpha_p(const float* lsig, const int* pptr,
                                            int has_p, float& alpha, float& pf,
                                            bool& fast) {
    float ls = lsig[0];
    alpha = -0.5f * __expf(-2.f * ls);   // < 0
    int praw = has_p ? *pptr : 2;
    pf = (praw > 0 && praw < 1000) ? (float)praw : __int_as_float(praw);
    fast = (pf == 2.0f);
}

// ---------------- kernel 1: norms + resets ----------------
__global__ void prep_norms(const float* __restrict__ z, const float* __restrict__ e) {
    int i = blockIdx.x * 256 + threadIdx.x;        // grid covers N_TOT
    {   // zsq directly from z: z[b][c][hw], coalesced per-k iteration
        int b = i >> 10, hw = i & 1023;
        const float* zp = z + (size_t)b * 65536 + hw;
        float a0 = 0.f, a1 = 0.f, a2 = 0.f, a3 = 0.f;
        #pragma unroll
        for (int k = 0; k < 64; k += 4) {
            float v0 = zp[(k + 0) * 1024];
            float v1 = zp[(k + 1) * 1024];
            float v2 = zp[(k + 2) * 1024];
            float v3 = zp[(k + 3) * 1024];
            a0 += v0 * v0; a1 += v1 * v1; a2 += v2 * v2; a3 += v3 * v3;
        }
        g_zsq[i] = (a0 + a1) + (a2 + a3);
    }
    if (i < M_TOT) {
        const float4* p = (const float4*)(e + (size_t)i * KDIM);
        float a0 = 0.f, a1 = 0.f, a2 = 0.f, a3 = 0.f;
        #pragma unroll
        for (int k = 0; k < 16; k++) {
            float4 v = p[k];
            a0 += v.x * v.x; a1 += v.y * v.y; a2 += v.z * v.z; a3 += v.w * v.w;
        }
        g_esq[i] = (a0 + a1) + (a2 + a3);
        g_wmax[i] = 0u;
    }
    if (i == 0) g_flagcnt = 0;
}

// ---------------- kernel 2: fused fp16 GEMM + wmax + lse partials ----------------
// Tile 128(n) x 128(m), 256 threads, K=64 in 4 k16 steps.
// Warp-tile N (32 cols) processed in TWO sequential halves of 16 cols to keep
// live registers < 128 (no spills at 2 CTAs/SM): per half acc[4][2][4].
// A holds -2*z so acc = -2*dot; d2 = zsq + esq + acc.
#define HPITCH_B 144                         // bytes per half-tile row
#define SM_A    0                            // 128*144 = 18432
#define SM_B    18432                        // 18432
#define SM_ZSQ  36864                        // 512
#define SM_ESQ  37376                        // 512
#define SM_MRG  37888                        // 3 * 1024
#define SMEM_BYTES 40960

__global__ __launch_bounds__(256, 2) void gemm_fused(const float* __restrict__ z,
                                                     const float* __restrict__ e,
                                                     const float* __restrict__ belong,
                                                     const float* __restrict__ lsig,
                                                     const int* __restrict__ pptr,
                                                     int has_p) {
    __shared__ __align__(16) unsigned char smraw[SMEM_BYTES];
    const uint32_t smb = s2u(smraw);

    const int tid = threadIdx.x;
    const int m0 = blockIdx.x * 128;
    const int n0 = blockIdx.y * 128;
    const int ntile = blockIdx.y;
    const int lane = tid & 31, wid = tid >> 5;

    float alpha, pf; bool fast;
    get_alpha_p(lsig, pptr, has_p, alpha, pf, fast);
    const float margin = -30.f / alpha;                // v-space contribution cutoff

    // ---- stage A = -2*z as half, layout [row][k] ----
    {
        const float* zb = z + (size_t)(n0 >> 10) * 65536 + (n0 & 1023);
        int ar_ = lane & 7, kq = lane >> 3;            // 8 rows x 4 kpairs per warp
        #pragma unroll
        for (int it = 0; it < 16; it++) {
            int g = (tid >> 5) + it * 8;               // 0..127
            int rb = g & 15, kb = g >> 4;              // 16 rowblocks, 8 kblocks
            int row = rb * 8 + ar_;
            int k = (kb * 4 + kq) * 2;
            float v0 = zb[(k + 0) * 1024 + row];
            float v1 = zb[(k + 1) * 1024 + row];
            __half2 h = __floats2half2_rn(-2.f * v0, -2.f * v1);
            *(__half2*)(smraw + SM_A + row * HPITCH_B + k * 2) = h;
        }
    }
    // ---- stage B = e as half ----
    #pragma unroll
    for (int it = 0; it < 8; it++) {
        int idx = tid + it * 256;                      // 0..2047
        int row = idx >> 4, c4 = idx & 15;
        float4 v = *(const float4*)(e + (size_t)(m0 + row) * KDIM + c4 * 4);
        __half2 h01 = __floats2half2_rn(v.x, v.y);
        __half2 h23 = __floats2half2_rn(v.z, v.w);
        uint2 u = make_uint2(*(uint32_t*)&h01, *(uint32_t*)&h23);
        *(uint2*)(smraw + SM_B + row * HPITCH_B + c4 * 8) = u;
    }
    float* szsq = (float*)(smraw + SM_ZSQ);
    float* sesq = (float*)(smraw + SM_ESQ);
    if (tid < 128) {
        szsq[tid] = g_zsq[n0 + tid];
        sesq[tid] = g_esq[m0 + tid];
    }
    __syncthreads();

    const int wm = wid >> 2;       // 0..1 (n halves)
    const int wn = wid & 3;        // 0..3 (m quarters)
    const int ar = lane >> 2, ac = lane & 3;

    // ldmatrix lane addressing
    const uint32_t a_base = smb + SM_A +
        (uint32_t)((wm * 64 + (lane & 7) + ((lane >> 3) & 1) * 8) * HPITCH_B) +
        ((lane >> 4) & 1) * 16;
    const uint32_t b_base = smb + SM_B +
        (uint32_t)((wn * 32 + (lane & 7) + ((lane >> 3) & 1) * 8) * HPITCH_B) +
        ((lane >> 4) & 1) * 16;

    float zsv[4][2];
    #pragma unroll
    for (int i = 0; i < 4; i++) {
        int lr0 = wm * 64 + i * 16 + ar;
        zsv[i][0] = szsq[lr0];
        zsv[i][1] = szsq[lr0 + 8];
    }

    float* sMD = (float*)(smraw + SM_MRG);
    float* sMS = sMD + 256;
    float* sMW = sMD + 512;

    // =================== two N-halves: mma + epilogue each ===================
    #pragma unroll 1
    for (int jh = 0; jh < 2; jh++) {
        const uint32_t b_base_h = b_base + (uint32_t)(jh * 16 * HPITCH_B);

        float acc[4][2][4];
        #pragma unroll
        for (int i = 0; i < 4; i++)
            #pragma unroll
            for (int j = 0; j < 2; j++)
                #pragma unroll
                for (int r = 0; r < 4; r++) acc[i][j][r] = 0.f;

        #pragma unroll
        for (int ks = 0; ks < 4; ks++) {
            uint32_t a[4][4], b[2][2];
            #pragma unroll
            for (int i = 0; i < 4; i++)
                ldsm4(a[i][0], a[i][1], a[i][2], a[i][3],
                      a_base + i * 16 * HPITCH_B + ks * 32);
            ldsm4(b[0][0], b[1][0], b[0][1], b[1][1], b_base_h + ks * 32);
            #pragma unroll
            for (int i = 0; i < 4; i++)
                #pragma unroll
                for (int j = 0; j < 2; j++)
                    mma_f16(acc[i][j], a[i], b[j][0], b[j][1]);
        }

        // ---- epilogue for 16 cols: d2, wmax, online lse (above-branch) ----
        float dmin_[2][2], s_[2][2], dthr_[2][2], wloc[2][2];
        #pragma unroll
        for (int j = 0; j < 2; j++)
            #pragma unroll
            for (int p_ = 0; p_ < 2; p_++) {
                dmin_[j][p_] = 1e19f; s_[j][p_] = 0.f;
                dthr_[j][p_] = 3.0e38f; wloc[j][p_] = 0.f;
            }

        float esv[2][2];
        #pragma unroll
        for (int j = 0; j < 2; j++) {
            int lc = wn * 32 + jh * 16 + j * 8 + 2 * ac;
            esv[j][0] = sesq[lc];
            esv[j][1] = sesq[lc + 1];
        }

        #pragma unroll
        for (int i = 0; i < 4; i++) {
            int lr0 = wm * 64 + i * 16 + ar;
            size_t gr0 = (size_t)(n0 + lr0) * M_TOT;
            size_t gr1 = (size_t)(n0 + lr0 + 8) * M_TOT;
            float zs0 = zsv[i][0], zs1 = zsv[i][1];

            // batch the 4 belong loads for this i (MLP)
            int gc0 = m0 + wn * 32 + jh * 16 + 2 * ac;
            float2 b00 = *(const float2*)(belong + gr0 + gc0);
            float2 b10 = *(const float2*)(belong + gr1 + gc0);
            float2 b01 = *(const float2*)(belong + gr0 + gc0 + 8);
            float2 b11 = *(const float2*)(belong + gr1 + gc0 + 8);

            #pragma unroll
            for (int j = 0; j < 2; j++) {
                float es0 = esv[j][0], es1 = esv[j][1];
                float d00 = (zs0 + es0) + acc[i][j][0];
                float d01 = (zs0 + es1) + acc[i][j][1];
                float d10 = (zs1 + es0) + acc[i][j][2];
                float d11 = (zs1 + es1) + acc[i][j][3];

                float2 b0 = (j == 0) ? b00 : b01;
                float2 b1 = (j == 0) ? b10 : b11;
                wloc[j][0] = fmaxf(wloc[j][0],
                                   fmaxf(b0.x * b0.x * d00, b1.x * b1.x * d10));
                wloc[j][1] = fmaxf(wloc[j][1],
                                   fmaxf(b0.y * b0.y * d01, b1.y * b1.y * d11));

                #pragma unroll
                for (int p_ = 0; p_ < 2; p_++) {
                    float da = (p_ == 0) ? d00 : d01;
                    float db = (p_ == 0) ? d10 : d11;
                    #pragma unroll
                    for (int hh = 0; hh < 2; hh++) {
                        float d2 = (hh == 0) ? da : db;
                        if (__builtin_expect(d2 < dthr_[j][p_], 0)) {
                            if (d2 < dmin_[j][p_]) {
                                float vold = vfun(dmin_[j][p_], fast, pf);
                                float vnew = vfun(d2, fast, pf);
                                s_[j][p_] = s_[j][p_] * __expf(alpha * (vold - vnew)) + 1.f;
                                dmin_[j][p_] = d2;
                                float vlim = vnew + margin;
                                dthr_[j][p_] = fast ? sqrtf(vlim) : __powf(vlim, 1.f / pf);
                            } else {
                                float v = vfun(d2, fast, pf);
                                float vm = vfun(dmin_[j][p_], fast, pf);
                                s_[j][p_] += __expf(alpha * (v - vm));
                            }
                        }
                    }
                }
            }
        }

        // ---- warp butterfly (xor 4,8,16): min(dmin), sum(s), max(w) ----
        #pragma unroll
        for (int j = 0; j < 2; j++)
            #pragma unroll
            for (int p_ = 0; p_ < 2; p_++) {
                float dm = dmin_[j][p_];
                #pragma unroll
                for (int off = 4; off < 32; off <<= 1)
                    dm = fminf(dm, __shfl_xor_sync(0xffffffffu, dm, off));
                float sv = s_[j][p_] *
                    __expf(alpha * (vfun(dmin_[j][p_], fast, pf) - vfun(dm, fast, pf)));
                #pragma unroll
                for (int off = 4; off < 32; off <<= 1)
                    sv += __shfl_xor_sync(0xffffffffu, sv, off);
                float wv = wloc[j][p_];
                #pragma unroll
                for (int off = 4; off < 32; off <<= 1)
                    wv = fmaxf(wv, __shfl_xor_sync(0xffffffffu, wv, off));
                if (lane < 4) {
                    int col = wn * 32 + jh * 16 + j * 8 + 2 * lane + p_;
                    sMD[wm * 128 + col] = dm;
                    sMS[wm * 128 + col] = sv;
                    sMW[wm * 128 + col] = wv;
                }
            }
    }
    __syncthreads();

    if (tid < 128) {
        int col = tid;
        float d0 = sMD[col], d1 = sMD[128 + col];
        float dm = fminf(d0, d1);
        float vm = vfun(dm, fast, pf);
        float s = sMS[col] * __expf(alpha * (vfun(d0, fast, pf) - vm))
                + sMS[128 + col] * __expf(alpha * (vfun(d1, fast, pf) - vm));
        g_pmin[ntile * M_TOT + m0 + col] = dm;
        g_psum[ntile * M_TOT + m0 + col] = s;
        atomicMax(&g_wmax[m0 + col],
                  __float_as_uint(fmaxf(sMW[col], sMW[128 + col])));
    }
}

// ---------------- kernel 3: newmax + combine tiles -> lse + flag ----------------
// grid 128 blocks x 256 threads: block handles 32 columns, 8 warps split 128 tiles.
__global__ void finalize_k(const float* __restrict__ maxd,
                           const float* __restrict__ lsig,
                           const int* __restrict__ pptr, int has_p) {
    __shared__ float s_t2[32];
    __shared__ float sdm[8][32];
    __shared__ float ssm[8][32];
    const int lane = threadIdx.x & 31;
    const int warp = threadIdx.x >> 5;
    const int col = blockIdx.x * 32 + lane;

    float alpha, pf; bool fast;
    get_alpha_p(lsig, pptr, has_p, alpha, pf, fast);

    if (threadIdx.x < 32) {   // EMA new_max for this block's 32 columns
        float bm = sqrtf(__uint_as_float(g_wmax[col]));
        float nm = fmaxf(0.999f * maxd[col] + 0.001f * bm, 1e-8f);
        g_t[col] = nm;
        g_t2[col] = nm * nm;
        s_t2[lane] = nm * nm;
    }

    float dmc = 3.0e38f, s = 0.f;
    #pragma unroll 4
    for (int t = warp * 16; t < warp * 16 + 16; t++) {
        float pm = g_pmin[t * M_TOT + col];
        float ps = g_psum[t * M_TOT + col];
        if (pm < dmc) {
            s = s * __expf(alpha * (vfun(dmc, fast, pf) - vfun(pm, fast, pf))) + ps;
            dmc = pm;
        } else {
            s += ps * __expf(alpha * (vfun(pm, fast, pf) - vfun(dmc, fast, pf)));
        }
    }
    sdm[warp][lane] = dmc;
    ssm[warp][lane] = s;
    __syncthreads();

    if (warp == 0) {
        float dall = 3.0e38f;
        #pragma unroll
        for (int w = 0; w < 8; w++) dall = fminf(dall, sdm[w][lane]);
        float vall = vfun(dall, fast, pf);
        float sall = 0.f;
        #pragma unroll
        for (int w = 0; w < 8; w++)
            sall += ssm[w][lane] * __expf(alpha * (vfun(sdm[w][lane], fast, pf) - vall));
        g_lse[col] = alpha * vall + logf(sall);
        if (dall < s_t2[lane]) {         // some element takes the below branch
            int idx = atomicAdd(&g_flagcnt, 1);
            g_flags[idx] = col;
        }
    }
}

// ---------------- kernel 4: exact recompute for flagged columns (rare) -------
__global__ void fixup_k(const float* __restrict__ z, const float* __restrict__ e,
                        const float* __restrict__ lsig,
                        const int* __restrict__ pptr, int has_p) {
    __shared__ float esm[64];
    __shared__ float red_v[256];
    __shared__ float red_s[256];
    const int tid = threadIdx.x;
    const int cnt = g_flagcnt;
    float alpha, pf; bool fast;
    get_alpha_p(lsig, pptr, has_p, alpha, pf, fast);
    const float elo = 2.f / pf, ehi = 2.f * pf;

    for (int f = blockIdx.x; f < cnt; f += gridDim.x) {
        int col = g_flags[f];
        if (tid < 64) esm[tid] = e[col * 64 + tid];
        __syncthreads();
        float t = g_t[col];
        float esq = g_esq[col];
        float vmin = 3.0e38f, s = 0.f;
        for (int n = tid; n < N_TOT; n += 256) {
            const float* zp = z + (size_t)(n >> 10) * 65536 + (n & 1023);
            float dot = 0.f;
            #pragma unroll
            for (int k = 0; k < 64; k++) dot += zp[k * 1024] * esm[k];
            float d2 = fmaxf(g_zsq[n] + esq - 2.f * dot, 0.f);
            float dist = sqrtf(d2);
            float v;
            if (fast) v = (dist < t) ? dist : d2 * d2;
            else      v = (dist < t) ? __powf(dist, elo) : __powf(dist, ehi);
            if (v < vmin) {
                s = s * __expf(alpha * (vmin - v)) + 1.f;
                vmin = v;
            } else {
                float a1 = alpha * (v - vmin);
                if (a1 > -30.f) s += __expf(a1);
            }
        }
        red_v[tid] = vmin; red_s[tid] = s;
        __syncthreads();
        if (tid == 0) {
            float vm = 3.0e38f;
            for (int i = 0; i < 256; i++) vm = fminf(vm, red_v[i]);
            float ss = 0.f;
            for (int i = 0; i < 256; i++)
                ss += red_s[i] * __expf(alpha * (red_v[i] - vm));
            g_lse[col] = alpha * vm + logf(ss);
        }
        __syncthreads();
    }
}

// ---------------- kernel 5: final reduction -> loss ----------------
__global__ void final_k(const float* __restrict__ lsig, float* __restrict__ out) {
    __shared__ double red[256];
    double a = 0.0;
    for (int i = threadIdx.x; i < M_TOT; i += 256) a += (double)g_lse[i];
    red[threadIdx.x] = a;
    __syncthreads();
    for (int st = 128; st > 0; st >>= 1) {
        if (threadIdx.x < st) red[threadIdx.x] += red[threadIdx.x + st];
        __syncthreads();
    }
    if (threadIdx.x == 0) {
        double ls = (double)lsig[0];
        out[0] = (float)(-(red[0] / (double)M_TOT) + (double)KDIM * ls);
    }
}

// ---------------- launch ----------------
extern "C" void kernel_launch(void* const* d_in, const int* in_sizes, int n_in,
                              void* d_out, int out_size) {
    const float* z      = (const float*)d_in[0];
    const float* e      = (const float*)d_in[1];
    const float* belong = (const float*)d_in[2];
    const float* lsig   = (const float*)d_in[3];
    const float* maxd   = (const float*)d_in[4];
    const int*   pptr   = (n_in > 5) ? (const int*)d_in[5] : nullptr;
    (void)in_sizes; (void)out_size;
    int has_p = pptr ? 1 : 0;

    prep_norms<<<N_TOT / 256, 256>>>(z, e);
    gemm_fused<<<dim3(MTILES, NTILES), 256>>>(z, e, belong, lsig, pptr, has_p);
    finalize_k<<<M_TOT / 32, 256>>>(maxd, lsig, pptr, has_p);
    fixup_k<<<64, 256>>>(z, e, lsig, pptr, has_p);
    final_k<<<1, 256>>>(lsig, (float*)d_out);
}